// round 3
// baseline (speedup 1.0000x reference)
#include <cuda_runtime.h>

#define THREADS 128
#define BPB 128      // batches per block
#define TT 8         // timesteps per tile
#define XGP 129      // padded batch stride in gate smem (gcd(129,32)=1 -> conflict-free)

// ---- fast-but-accurate activations (ex2-based, ~1e-7 rel err) ----
__device__ __forceinline__ float sigm(float x){
  return __fdividef(1.f, 1.f + __expf(-x));
}
__device__ __forceinline__ float tanh_acc(float x){
  // 1 - 2/(e^{2x}+1): exact cancellation behavior for small |x|, saturates correctly
  return 1.f - __fdividef(2.f, __expf(2.f*x) + 1.f);
}

// ---- packed f32x2 helpers (FFMA2: 2x FMA throughput, ptxas won't auto-fuse) ----
__device__ __forceinline__ void fma2(unsigned long long &d, unsigned long long a, unsigned long long b){
  asm("fma.rn.f32x2 %0, %1, %2, %0;" : "+l"(d) : "l"(a), "l"(b));
}
__device__ __forceinline__ unsigned long long pack2(float lo, float hi){
  unsigned long long r; asm("mov.b64 %0, {%1,%2};" : "=l"(r) : "f"(lo), "f"(hi)); return r;
}
__device__ __forceinline__ void unpack2(unsigned long long v, float &lo, float &hi){
  asm("mov.b64 {%0,%1}, %2;" : "=f"(lo), "=f"(hi) : "l"(v));
}

// dynamic smem layout (floats):
//  [0,6400)        s_w1 : W1 transposed  [t*64 + j]
//  [6400,10496)    s_w2 : W2 transposed  [j*64 + k]
//  [10496,10624)   s_w3 : W3 raw (2x64)
//  [10624,14752)   s_xg : gate tile [ (s*4+g)*129 + b ]
#define SMEM_FLOATS 14752

__global__ __launch_bounds__(THREADS, 3)
void lstm_fused(const float* __restrict__ X,   const float* __restrict__ Wih,
                const float* __restrict__ Whh, const float* __restrict__ bih,
                const float* __restrict__ bhh, const float* __restrict__ W1,
                const float* __restrict__ b1,  const float* __restrict__ W2,
                const float* __restrict__ b2,  const float* __restrict__ W3,
                const float* __restrict__ b3,  float* __restrict__ out)
{
  extern __shared__ float sm[];
  float* s_w1 = sm;           // 6400
  float* s_w2 = sm + 6400;    // 4096
  float* s_w3 = sm + 10496;   // 128
  float* s_xg = sm + 10624;   // 32*129

  const int tid  = threadIdx.x;
  const int lane = tid & 31;
  const int wid  = tid >> 5;
  const int b0   = blockIdx.x * BPB;

  // ---- stage weights (once per block) ----
  for (int i = tid; i < 6400; i += THREADS){      // coalesced read, transposed store
    int t = i % 100, j = i / 100;                 // W1[i] == W1[j][t]
    s_w1[t*64 + j] = W1[i];
  }
  for (int i = tid; i < 4096; i += THREADS){      // W2[i] == W2[k][j]
    int k = i >> 6, j = i & 63;
    s_w2[j*64 + k] = W2[i];
  }
  if (tid < 128) s_w3[tid] = W3[tid];

  // ---- producer per-lane constants ----
  const int dblk = lane & 3;                      // which 4-wide chunk of D=16
  const float4 wgA = *(const float4*)(Wih +  0 + dblk*4);
  const float4 wgB = *(const float4*)(Wih + 16 + dblk*4);
  const float4 wgC = *(const float4*)(Wih + 32 + dblk*4);
  const float4 wgD = *(const float4*)(Wih + 48 + dblk*4);
  const float bsum = bih[dblk] + bhh[dblk];       // bias for the gate THIS lane stores

  // ---- consumer per-thread state ----
  const float whh0 = Whh[0], whh1 = Whh[1], whh2 = Whh[2], whh3 = Whh[3];
  float h = 0.f, c = 0.f;
  unsigned long long acc[32];                     // 64 y1 accumulators as f32x2 pairs
  #pragma unroll
  for (int j = 0; j < 32; j++) acc[j] = 0ull;

  __syncthreads();

  for (int t0 = 0; t0 < 100; t0 += TT){
    const int tt  = min(TT, 100 - t0);
    const int s   = lane >> 2;                    // step within tile handled by this lane
    const bool act = (s < tt);

    // ==== producer: each warp handles 32 batch rows; 512B coalesced load per row ====
    for (int r4 = 0; r4 < 32; r4 += 4){
      float4 xv[4];
      #pragma unroll
      for (int q = 0; q < 4; q++){                // batch 4 loads -> MLP=4
        int b = wid*32 + r4 + q;
        const float4* p = (const float4*)(X + ((size_t)(b0 + b)*100 + t0)*16) + lane;
        xv[q] = act ? __ldg(p) : make_float4(0.f,0.f,0.f,0.f);
      }
      #pragma unroll
      for (int q = 0; q < 4; q++){
        int b = wid*32 + r4 + q;
        float4 x = xv[q];
        // per-lane partial dot for all 4 gates (this lane's 4 of 16 D-values)
        float p0 = x.x*wgA.x + x.y*wgA.y + x.z*wgA.z + x.w*wgA.w;
        float p1 = x.x*wgB.x + x.y*wgB.y + x.z*wgB.z + x.w*wgB.w;
        float p2 = x.x*wgC.x + x.y*wgC.y + x.z*wgC.z + x.w*wgC.w;
        float p3 = x.x*wgD.x + x.y*wgD.y + x.z*wgD.z + x.w*wgD.w;
        // reduce across the 4 lanes of this step-group
        p0 += __shfl_xor_sync(0xffffffffu, p0, 1);
        p1 += __shfl_xor_sync(0xffffffffu, p1, 1);
        p2 += __shfl_xor_sync(0xffffffffu, p2, 1);
        p3 += __shfl_xor_sync(0xffffffffu, p3, 1);
        p0 += __shfl_xor_sync(0xffffffffu, p0, 2);
        p1 += __shfl_xor_sync(0xffffffffu, p1, 2);
        p2 += __shfl_xor_sync(0xffffffffu, p2, 2);
        p3 += __shfl_xor_sync(0xffffffffu, p3, 2);
        float gv = (dblk==0) ? p0 : (dblk==1) ? p1 : (dblk==2) ? p2 : p3;
        if (act) s_xg[(s*4 + dblk)*XGP + b] = gv + bsum;  // stride-129 scatter: conflict-free
      }
    }
    __syncthreads();

    // ==== consumer: thread tid owns batch b0+tid; scan + fused W1 accumulation ====
    for (int s2 = 0; s2 < tt; s2++){
      float g0 = s_xg[(s2*4+0)*XGP + tid];        // stride-1 across threads
      float g1 = s_xg[(s2*4+1)*XGP + tid];
      float g2 = s_xg[(s2*4+2)*XGP + tid];
      float g3 = s_xg[(s2*4+3)*XGP + tid];
      float gi = sigm(g0 + h*whh0);
      float gf = sigm(g1 + h*whh1);
      float gg = tanh_acc(g2 + h*whh2);
      float go = sigm(g3 + h*whh3);
      c = gf*c + gi*gg;
      h = go * tanh_acc(c);
      float hr = fmaxf(h, 0.f);
      unsigned long long hp = pack2(hr, hr);
      const ulonglong2* wv = (const ulonglong2*)(s_w1 + (t0 + s2)*64);  // broadcast
      #pragma unroll
      for (int j = 0; j < 16; j++){
        ulonglong2 w = wv[j];
        fma2(acc[2*j],   hp, w.x);
        fma2(acc[2*j+1], hp, w.y);
      }
    }
    __syncthreads();
  }

  // ==== MLP layers 2/3 + log_softmax (per thread) ====
  unsigned long long z[32];
  #pragma unroll
  for (int k = 0; k < 32; k++) z[k] = 0ull;
  #pragma unroll
  for (int j2 = 0; j2 < 32; j2++){
    float a0, a1; unpack2(acc[j2], a0, a1);
    a0 = fmaxf(a0 + __ldg(b1 + 2*j2  ), 0.f);
    a1 = fmaxf(a1 + __ldg(b1 + 2*j2+1), 0.f);
    unsigned long long a0p = pack2(a0, a0), a1p = pack2(a1, a1);
    const ulonglong2* w20 = (const ulonglong2*)(s_w2 + (2*j2  )*64);
    const ulonglong2* w21 = (const ulonglong2*)(s_w2 + (2*j2+1)*64);
    #pragma unroll
    for (int k = 0; k < 16; k++){
      ulonglong2 wa = w20[k], wb = w21[k];
      fma2(z[2*k],   a0p, wa.x); fma2(z[2*k+1], a0p, wa.y);
      fma2(z[2*k],   a1p, wb.x); fma2(z[2*k+1], a1p, wb.y);
    }
  }
  float y0 = __ldg(b3), y1 = __ldg(b3 + 1);
  #pragma unroll
  for (int k2 = 0; k2 < 32; k2++){
    float z0, z1; unpack2(z[k2], z0, z1);
    z0 = fmaxf(z0 + __ldg(b2 + 2*k2  ), 0.f);
    z1 = fmaxf(z1 + __ldg(b2 + 2*k2+1), 0.f);
    y0 += z0*s_w3[2*k2]      + z1*s_w3[2*k2+1];
    y1 += z0*s_w3[64 + 2*k2] + z1*s_w3[64 + 2*k2+1];
  }
  float m   = fmaxf(y0, y1);
  float lse = m + __logf(__expf(y0 - m) + __expf(y1 - m));
  ((float2*)out)[b0 + tid] = make_float2(y0 - lse, y1 - lse);
}

extern "C" void kernel_launch(void* const* d_in, const int* in_sizes, int n_in,
                              void* d_out, int out_size)
{
  const float* X   = (const float*)d_in[0];
  const float* Wih = (const float*)d_in[1];
  const float* Whh = (const float*)d_in[2];
  const float* bih = (const float*)d_in[3];
  const float* bhh = (const float*)d_in[4];
  const float* W1  = (const float*)d_in[5];
  const float* b1  = (const float*)d_in[6];
  const float* W2  = (const float*)d_in[7];
  const float* b2  = (const float*)d_in[8];
  const float* W3  = (const float*)d_in[9];
  const float* b3  = (const float*)d_in[10];

  const size_t smem = SMEM_FLOATS * sizeof(float);   // 59008 B > 48K default
  cudaFuncSetAttribute(lstm_fused, cudaFuncAttributeMaxDynamicSharedMemorySize, (int)smem);
  lstm_fused<<<65536 / BPB, THREADS, smem>>>(X, Wih, Whh, bih, bhh,
                                             W1, b1, W2, b2, W3, b3,
                                             (float*)d_out);
}

// round 4
// speedup vs baseline: 2.0595x; 2.0595x over previous
#include <cuda_runtime.h>

#define NB 65536
#define NT 100

// 105 MB gate scratch: layout [t][b] -> float4 (4 gate pre-activations)
__device__ float4 g_scratch[NB * NT];

// ---- fast-but-accurate activations ----
__device__ __forceinline__ float sigm(float x){
  return __fdividef(1.f, 1.f + __expf(-x));
}
__device__ __forceinline__ float tanh_acc(float x){
  return 1.f - __fdividef(2.f, __expf(2.f*x) + 1.f);
}

// ---- packed f32x2 helpers ----
__device__ __forceinline__ void fma2(unsigned long long &d, unsigned long long a, unsigned long long b){
  asm("fma.rn.f32x2 %0, %1, %2, %0;" : "+l"(d) : "l"(a), "l"(b));
}
__device__ __forceinline__ unsigned long long pack2(float lo, float hi){
  unsigned long long r; asm("mov.b64 %0, {%1,%2};" : "=l"(r) : "f"(lo), "f"(hi)); return r;
}
__device__ __forceinline__ void unpack2(unsigned long long v, float &lo, float &hi){
  asm("mov.b64 {%0,%1}, %2;" : "=f"(lo), "=f"(hi) : "l"(v));
}

// ============================================================================
// Kernel A: gate precompute. Warp tile = 4 batches x 2 timesteps.
// lane -> b_i = lane>>3, t_i = (lane>>2)&1, dblk = lane&3.
// Read: per lane one float4; warp reads 4 full 128B lines (perfectly coalesced).
// 3-shfl butterfly transpose-reduce leaves lane holding gate[dblk] for (b_i,t_i).
// Write: two contiguous 64B chunks per warp into [t][b][g] layout.
// ============================================================================
__global__ __launch_bounds__(512)
void gates_kernel(const float* __restrict__ X,   const float* __restrict__ Wih,
                  const float* __restrict__ bih, const float* __restrict__ bhh)
{
  const int lane = threadIdx.x & 31;
  const int wg   = (blockIdx.x * 512 + threadIdx.x) >> 5;   // 0..16383
  const int b_i  = lane >> 3;
  const int t_i  = (lane >> 2) & 1;
  const int dblk = lane & 3;
  const int b    = wg * 4 + b_i;

  const float4 w0 = *(const float4*)(Wih +  0 + dblk*4);
  const float4 w1 = *(const float4*)(Wih + 16 + dblk*4);
  const float4 w2 = *(const float4*)(Wih + 32 + dblk*4);
  const float4 w3 = *(const float4*)(Wih + 48 + dblk*4);
  const float bsum = bih[dblk] + bhh[dblk];

  // float4 index into X for (b, t_i) chunk dblk
  const float4* xp = (const float4*)X + (size_t)(b * NT + t_i) * 4 + dblk;
  // float index into scratch for (t_i, b) gate dblk
  float* sp = (float*)g_scratch + ((size_t)t_i * NB + b) * 4 + dblk;

  #pragma unroll 1
  for (int t0 = 0; t0 < NT; t0 += 4){
    float4 xa = __ldg(xp);          // (b, t0+t_i)
    float4 xb = __ldg(xp + 8);      // (b, t0+2+t_i)
    xp += 16;

    #pragma unroll
    for (int q = 0; q < 2; q++){
      float4 x = q ? xb : xa;
      float p0 = x.x*w0.x + x.y*w0.y + x.z*w0.z + x.w*w0.w;
      float p1 = x.x*w1.x + x.y*w1.y + x.z*w1.z + x.w*w1.w;
      float p2 = x.x*w2.x + x.y*w2.y + x.z*w2.z + x.w*w2.w;
      float p3 = x.x*w3.x + x.y*w3.y + x.z*w3.z + x.w*w3.w;
      // butterfly transpose-reduce over the 4-lane group (3 shfl total)
      float s01 = (dblk & 1) ? p0 : p1;
      float r01 = __shfl_xor_sync(0xffffffffu, s01, 1);
      float a   = ((dblk & 1) ? p1 : p0) + r01;
      float s23 = (dblk & 1) ? p2 : p3;
      float r23 = __shfl_xor_sync(0xffffffffu, s23, 1);
      float bb  = ((dblk & 1) ? p3 : p2) + r23;
      float snd = (dblk & 2) ? a : bb;
      float rcv = __shfl_xor_sync(0xffffffffu, snd, 2);
      float gv  = ((dblk & 2) ? bb : a) + rcv + bsum;
      sp[(size_t)(q * 2) * NB * 4] = gv;
    }
    sp += (size_t)4 * NB * 4;
  }
}

// ============================================================================
// Kernel B: per-batch LSTM scan + fused W1 + MLP head + log_softmax.
// Thread = batch. Gates read as coalesced float4 (512B/warp/step), 4-deep.
// smem: s_w1 (W1^T, 6400) + s_w2 (W2^T, 4096) + s_w3 (128) = 42496 B.
// ============================================================================
#define SMB_FLOATS 10624

__global__ __launch_bounds__(128, 3)
void scan_kernel(const float* __restrict__ Whh, const float* __restrict__ W1,
                 const float* __restrict__ b1,  const float* __restrict__ W2,
                 const float* __restrict__ b2,  const float* __restrict__ W3,
                 const float* __restrict__ b3,  float* __restrict__ out)
{
  extern __shared__ float sm[];
  float* s_w1 = sm;           // [t*64 + j]
  float* s_w2 = sm + 6400;    // [j*64 + k]
  float* s_w3 = sm + 10496;   // raw 2x64

  const int tid = threadIdx.x;
  const int b   = blockIdx.x * 128 + tid;

  for (int i = tid; i < 6400; i += 128){      // W1[i] == W1[j][t]
    int t = i % 100, j = i / 100;
    s_w1[t*64 + j] = W1[i];
  }
  for (int i = tid; i < 4096; i += 128){      // W2[i] == W2[k][j]
    int k = i >> 6, j = i & 63;
    s_w2[j*64 + k] = W2[i];
  }
  if (tid < 128) s_w3[tid] = W3[tid];

  const float whh0 = Whh[0], whh1 = Whh[1], whh2 = Whh[2], whh3 = Whh[3];
  float h = 0.f, c = 0.f;
  unsigned long long acc[32];
  #pragma unroll
  for (int j = 0; j < 32; j++) acc[j] = 0ull;

  __syncthreads();

  const float4* gp = g_scratch + b;           // stride NB per step

  #pragma unroll 1
  for (int t0 = 0; t0 < NT; t0 += 4){
    float4 gq[4];
    gq[0] = __ldg(gp);
    gq[1] = __ldg(gp + NB);
    gq[2] = __ldg(gp + 2*NB);
    gq[3] = __ldg(gp + 3*NB);
    gp += 4*NB;

    #pragma unroll
    for (int s = 0; s < 4; s++){
      float4 g4 = gq[s];
      float gi = sigm(g4.x + h*whh0);
      float gf = sigm(g4.y + h*whh1);
      float gg = tanh_acc(g4.z + h*whh2);
      float go = sigm(g4.w + h*whh3);
      c = gf*c + gi*gg;
      h = go * tanh_acc(c);
      float hr = fmaxf(h, 0.f);
      unsigned long long hp = pack2(hr, hr);
      const ulonglong2* wv = (const ulonglong2*)(s_w1 + (t0 + s)*64);  // broadcast
      #pragma unroll
      for (int j = 0; j < 16; j++){
        ulonglong2 w = wv[j];
        fma2(acc[2*j],   hp, w.x);
        fma2(acc[2*j+1], hp, w.y);
      }
    }
  }

  // ==== MLP layers 2/3 + log_softmax ====
  unsigned long long z[32];
  #pragma unroll
  for (int k = 0; k < 32; k++) z[k] = 0ull;
  #pragma unroll
  for (int j2 = 0; j2 < 32; j2++){
    float a0, a1; unpack2(acc[j2], a0, a1);
    a0 = fmaxf(a0 + __ldg(b1 + 2*j2  ), 0.f);
    a1 = fmaxf(a1 + __ldg(b1 + 2*j2+1), 0.f);
    unsigned long long a0p = pack2(a0, a0), a1p = pack2(a1, a1);
    const ulonglong2* w20 = (const ulonglong2*)(s_w2 + (2*j2  )*64);
    const ulonglong2* w21 = (const ulonglong2*)(s_w2 + (2*j2+1)*64);
    #pragma unroll
    for (int k = 0; k < 16; k++){
      ulonglong2 wa = w20[k], wb = w21[k];
      fma2(z[2*k],   a0p, wa.x); fma2(z[2*k+1], a0p, wa.y);
      fma2(z[2*k],   a1p, wb.x); fma2(z[2*k+1], a1p, wb.y);
    }
  }
  float y0 = __ldg(b3), y1 = __ldg(b3 + 1);
  #pragma unroll
  for (int k2 = 0; k2 < 32; k2++){
    float z0, z1; unpack2(z[k2], z0, z1);
    z0 = fmaxf(z0 + __ldg(b2 + 2*k2  ), 0.f);
    z1 = fmaxf(z1 + __ldg(b2 + 2*k2+1), 0.f);
    y0 += z0*s_w3[2*k2]      + z1*s_w3[2*k2+1];
    y1 += z0*s_w3[64 + 2*k2] + z1*s_w3[64 + 2*k2+1];
  }
  float m   = fmaxf(y0, y1);
  float lse = m + __logf(__expf(y0 - m) + __expf(y1 - m));
  ((float2*)out)[b] = make_float2(y0 - lse, y1 - lse);
}

extern "C" void kernel_launch(void* const* d_in, const int* in_sizes, int n_in,
                              void* d_out, int out_size)
{
  const float* X   = (const float*)d_in[0];
  const float* Wih = (const float*)d_in[1];
  const float* Whh = (const float*)d_in[2];
  const float* bih = (const float*)d_in[3];
  const float* bhh = (const float*)d_in[4];
  const float* W1  = (const float*)d_in[5];
  const float* b1  = (const float*)d_in[6];
  const float* W2  = (const float*)d_in[7];
  const float* b2  = (const float*)d_in[8];
  const float* W3  = (const float*)d_in[9];
  const float* b3  = (const float*)d_in[10];

  // Kernel A: 16384 warps = 1024 blocks x 512 threads (4 batches per warp)
  gates_kernel<<<1024, 512>>>(X, Wih, bih, bhh);

  // Kernel B: thread-per-batch scan + head
  const size_t smem = SMB_FLOATS * sizeof(float);   // 42496 B (<= 48K default)
  scan_kernel<<<NB / 128, 128, smem>>>(Whh, W1, b1, W2, b2, W3, b3, (float*)d_out);
}

// round 5
// speedup vs baseline: 2.5606x; 1.2433x over previous
#include <cuda_runtime.h>

#define NB 65536
#define NT 100

// 105 MB gate scratch: layout [t][b] -> float4 (4 gate pre-activations)
__device__ float4 g_scratch[NB * NT];

// ---- activations ----
__device__ __forceinline__ float sigm(float x){
  return __fdividef(1.f, 1.f + __expf(-x));
}
__device__ __forceinline__ float tanh_acc(float x){
  return 1.f - __fdividef(2.f, __expf(2.f*x) + 1.f);
}

// ---- packed f32x2 helpers ----
__device__ __forceinline__ void fma2(unsigned long long &d, unsigned long long a, unsigned long long b){
  asm("fma.rn.f32x2 %0, %1, %2, %0;" : "+l"(d) : "l"(a), "l"(b));
}
__device__ __forceinline__ unsigned long long pack2(float lo, float hi){
  unsigned long long r; asm("mov.b64 %0, {%1,%2};" : "=l"(r) : "f"(lo), "f"(hi)); return r;
}
__device__ __forceinline__ void unpack2(unsigned long long v, float &lo, float &hi){
  asm("mov.b64 {%0,%1}, %2;" : "=f"(lo), "=f"(hi) : "l"(v));
}

// per-lane partial dots + 3-shfl butterfly transpose-reduce over the 4-lane group
__device__ __forceinline__ float gate_reduce(float4 x,
    const float4 &w0, const float4 &w1, const float4 &w2, const float4 &w3,
    int dblk, float bsum)
{
  float p0 = x.x*w0.x + x.y*w0.y + x.z*w0.z + x.w*w0.w;
  float p1 = x.x*w1.x + x.y*w1.y + x.z*w1.z + x.w*w1.w;
  float p2 = x.x*w2.x + x.y*w2.y + x.z*w2.z + x.w*w2.w;
  float p3 = x.x*w3.x + x.y*w3.y + x.z*w3.z + x.w*w3.w;
  float s01 = (dblk & 1) ? p0 : p1;
  float r01 = __shfl_xor_sync(0xffffffffu, s01, 1);
  float a   = ((dblk & 1) ? p1 : p0) + r01;
  float s23 = (dblk & 1) ? p2 : p3;
  float r23 = __shfl_xor_sync(0xffffffffu, s23, 1);
  float bb  = ((dblk & 1) ? p3 : p2) + r23;
  float snd = (dblk & 2) ? a : bb;
  float rcv = __shfl_xor_sync(0xffffffffu, snd, 2);
  return ((dblk & 2) ? bb : a) + rcv + bsum;
}

// ============================================================================
// Kernel A: gate precompute. Warp tile = 4 batches x 2 timesteps per store set,
// 8 timesteps per loop iter (4 independent LDG.128 -> MLP 4).
// 512 blocks x 512 threads = 8192 warps, each covering 2 batch-groups: 1 wave.
// ============================================================================
__global__ __launch_bounds__(512)
void gates_kernel(const float* __restrict__ X,   const float* __restrict__ Wih,
                  const float* __restrict__ bih, const float* __restrict__ bhh)
{
  const int lane = threadIdx.x & 31;
  const int wg   = (blockIdx.x * 512 + threadIdx.x) >> 5;   // 0..8191
  const int b_i  = lane >> 3;
  const int t_i  = (lane >> 2) & 1;
  const int dblk = lane & 3;

  const float4 w0 = *(const float4*)(Wih +  0 + dblk*4);
  const float4 w1 = *(const float4*)(Wih + 16 + dblk*4);
  const float4 w2 = *(const float4*)(Wih + 32 + dblk*4);
  const float4 w3 = *(const float4*)(Wih + 48 + dblk*4);
  const float bsum = bih[dblk] + bhh[dblk];

  #pragma unroll 1
  for (int rep = 0; rep < 2; rep++){
    const int b = (wg + rep*8192)*4 + b_i;
    const float4* xp = (const float4*)X + ((size_t)b*NT + t_i)*4 + dblk;
    float* sp = (float*)g_scratch + ((size_t)t_i*NB + b)*4 + dblk;

    #pragma unroll 1
    for (int t0 = 0; t0 < 96; t0 += 8){
      float4 xv[4];
      xv[0] = __ldg(xp);        // t = t0 + t_i
      xv[1] = __ldg(xp + 8);    // t = t0 + t_i + 2
      xv[2] = __ldg(xp + 16);   // t = t0 + t_i + 4
      xv[3] = __ldg(xp + 24);   // t = t0 + t_i + 6
      xp += 32;
      #pragma unroll
      for (int q = 0; q < 4; q++){
        float gv = gate_reduce(xv[q], w0, w1, w2, w3, dblk, bsum);
        sp[(size_t)(2*q)*NB*4] = gv;
      }
      sp += (size_t)8*NB*4;
    }
    // tail: t0 = 96..99
    {
      float4 xa = __ldg(xp), xb = __ldg(xp + 8);
      float ga = gate_reduce(xa, w0, w1, w2, w3, dblk, bsum);
      float gb = gate_reduce(xb, w0, w1, w2, w3, dblk, bsum);
      sp[0] = ga;
      sp[(size_t)2*NB*4] = gb;
    }
  }
}

// ============================================================================
// Kernel B: per-batch LSTM scan + fused W1 + MLP head + log_softmax.
// 512 blocks x 128 threads, 4 blocks/SM (single wave). Prefetched gate loads.
// smem: s_w1 (W1^T, 6400) + s_w2 (W2^T, 4096) + s_w3 (128) = 42496 B.
// ============================================================================
#define SMB_FLOATS 10624

__global__ __launch_bounds__(128, 4)
void scan_kernel(const float* __restrict__ Whh, const float* __restrict__ W1,
                 const float* __restrict__ b1,  const float* __restrict__ W2,
                 const float* __restrict__ b2,  const float* __restrict__ W3,
                 const float* __restrict__ b3,  float* __restrict__ out)
{
  extern __shared__ float sm[];
  float* s_w1 = sm;           // [t*64 + j]
  float* s_w2 = sm + 6400;    // [j*64 + k]
  float* s_w3 = sm + 10496;   // raw 2x64

  const int tid = threadIdx.x;
  const int b   = blockIdx.x * 128 + tid;

  for (int i = tid; i < 6400; i += 128){      // W1[i] == W1[j][t]
    int t = i % 100, j = i / 100;
    s_w1[t*64 + j] = W1[i];
  }
  for (int i = tid; i < 4096; i += 128){      // W2[i] == W2[k][j]
    int k = i >> 6, j = i & 63;
    s_w2[j*64 + k] = W2[i];
  }
  if (tid < 128) s_w3[tid] = W3[tid];

  const float whh0 = Whh[0], whh1 = Whh[1], whh2 = Whh[2], whh3 = Whh[3];
  float h = 0.f, c = 0.f;
  unsigned long long acc[32];
  #pragma unroll
  for (int j = 0; j < 32; j++) acc[j] = 0ull;

  __syncthreads();

  const float4* gp = g_scratch + b;           // stride NB per step
  float4 gq[4];
  gq[0] = __ldg(gp);
  gq[1] = __ldg(gp + NB);
  gq[2] = __ldg(gp + 2*NB);
  gq[3] = __ldg(gp + 3*NB);
  gp += 4*NB;

  #pragma unroll 1
  for (int t0 = 0; t0 < NT - 4; t0 += 4){
    // prefetch next 4 steps before consuming current
    float4 gn[4];
    gn[0] = __ldg(gp);
    gn[1] = __ldg(gp + NB);
    gn[2] = __ldg(gp + 2*NB);
    gn[3] = __ldg(gp + 3*NB);
    gp += 4*NB;

    #pragma unroll
    for (int s = 0; s < 4; s++){
      float4 g4 = gq[s];
      float gi = sigm(g4.x + h*whh0);
      float gf = sigm(g4.y + h*whh1);
      float gg = tanh_acc(g4.z + h*whh2);
      float go = sigm(g4.w + h*whh3);
      c = gf*c + gi*gg;
      h = go * tanh_acc(c);
      float hr = fmaxf(h, 0.f);
      unsigned long long hp = pack2(hr, hr);
      const ulonglong2* wv = (const ulonglong2*)(s_w1 + (t0 + s)*64);
      #pragma unroll
      for (int j = 0; j < 16; j++){
        ulonglong2 w = wv[j];
        fma2(acc[2*j],   hp, w.x);
        fma2(acc[2*j+1], hp, w.y);
      }
    }
    #pragma unroll
    for (int q = 0; q < 4; q++) gq[q] = gn[q];
  }
  // last 4 steps (t0 = 96)
  #pragma unroll
  for (int s = 0; s < 4; s++){
    float4 g4 = gq[s];
    float gi = sigm(g4.x + h*whh0);
    float gf = sigm(g4.y + h*whh1);
    float gg = tanh_acc(g4.z + h*whh2);
    float go = sigm(g4.w + h*whh3);
    c = gf*c + gi*gg;
    h = go * tanh_acc(c);
    float hr = fmaxf(h, 0.f);
    unsigned long long hp = pack2(hr, hr);
    const ulonglong2* wv = (const ulonglong2*)(s_w1 + (96 + s)*64);
    #pragma unroll
    for (int j = 0; j < 16; j++){
      ulonglong2 w = wv[j];
      fma2(acc[2*j],   hp, w.x);
      fma2(acc[2*j+1], hp, w.y);
    }
  }

  // ==== MLP layers 2/3 + log_softmax, in two 32-output halves (reg pressure) ====
  float y0 = __ldg(b3), y1 = __ldg(b3 + 1);
  #pragma unroll 1
  for (int half = 0; half < 2; half++){
    unsigned long long z[16];
    #pragma unroll
    for (int k = 0; k < 16; k++) z[k] = 0ull;
    #pragma unroll
    for (int j2 = 0; j2 < 32; j2++){
      float a0, a1; unpack2(acc[j2], a0, a1);
      a0 = fmaxf(a0 + __ldg(b1 + 2*j2  ), 0.f);
      a1 = fmaxf(a1 + __ldg(b1 + 2*j2+1), 0.f);
      unsigned long long a0p = pack2(a0, a0), a1p = pack2(a1, a1);
      const ulonglong2* w20 = (const ulonglong2*)(s_w2 + (2*j2  )*64 + half*32);
      const ulonglong2* w21 = (const ulonglong2*)(s_w2 + (2*j2+1)*64 + half*32);
      #pragma unroll
      for (int k = 0; k < 8; k++){
        ulonglong2 wa = w20[k], wb = w21[k];
        fma2(z[2*k],   a0p, wa.x); fma2(z[2*k+1], a0p, wa.y);
        fma2(z[2*k],   a1p, wb.x); fma2(z[2*k+1], a1p, wb.y);
      }
    }
    #pragma unroll
    for (int k2 = 0; k2 < 16; k2++){
      float z0, z1; unpack2(z[k2], z0, z1);
      int idx = half*32 + 2*k2;
      z0 = fmaxf(z0 + __ldg(b2 + idx    ), 0.f);
      z1 = fmaxf(z1 + __ldg(b2 + idx + 1), 0.f);
      y0 += z0*s_w3[idx]      + z1*s_w3[idx+1];
      y1 += z0*s_w3[64 + idx] + z1*s_w3[64 + idx+1];
    }
  }
  float m   = fmaxf(y0, y1);
  float lse = m + __logf(__expf(y0 - m) + __expf(y1 - m));
  ((float2*)out)[b] = make_float2(y0 - lse, y1 - lse);
}

extern "C" void kernel_launch(void* const* d_in, const int* in_sizes, int n_in,
                              void* d_out, int out_size)
{
  const float* X   = (const float*)d_in[0];
  const float* Wih = (const float*)d_in[1];
  const float* Whh = (const float*)d_in[2];
  const float* bih = (const float*)d_in[3];
  const float* bhh = (const float*)d_in[4];
  const float* W1  = (const float*)d_in[5];
  const float* b1  = (const float*)d_in[6];
  const float* W2  = (const float*)d_in[7];
  const float* b2  = (const float*)d_in[8];
  const float* W3  = (const float*)d_in[9];
  const float* b3  = (const float*)d_in[10];

  // Kernel A: 512 blocks x 512 threads, 2 batch-groups per warp -> single wave
  gates_kernel<<<512, 512>>>(X, Wih, bih, bhh);

  // Kernel B: thread-per-batch scan + head, 4 blocks/SM -> single wave
  const size_t smem = SMB_FLOATS * sizeof(float);   // 42496 B
  scan_kernel<<<NB / 128, 128, smem>>>(Whh, W1, b1, W2, b2, W3, b3, (float*)d_out);
}

// round 6
// speedup vs baseline: 2.6997x; 1.0543x over previous
#include <cuda_runtime.h>

#define NB 65536
#define NT 100
#define CH 20            // scan steps per chunk
#define HRS 132          // hr_buf row stride (floats)
#define Y1S 132          // y1buf row stride (floats)

// 105 MB gate scratch: layout [t][b] -> float4 (4 gate pre-activations)
__device__ float4 g_scratch[NB * NT];

// ---- activations ----
__device__ __forceinline__ float sigm(float x){
  return __fdividef(1.f, 1.f + __expf(-x));
}
__device__ __forceinline__ float tanh_acc(float x){
  return 1.f - __fdividef(2.f, __expf(2.f*x) + 1.f);
}

// ---- packed f32x2 helpers ----
__device__ __forceinline__ void fma2(unsigned long long &d, unsigned long long a, unsigned long long b){
  asm("fma.rn.f32x2 %0, %1, %2, %0;" : "+l"(d) : "l"(a), "l"(b));
}
__device__ __forceinline__ unsigned long long pack2(float lo, float hi){
  unsigned long long r; asm("mov.b64 %0, {%1,%2};" : "=l"(r) : "f"(lo), "f"(hi)); return r;
}
__device__ __forceinline__ void unpack2(unsigned long long v, float &lo, float &hi){
  asm("mov.b64 {%0,%1}, %2;" : "=f"(lo), "=f"(hi) : "l"(v));
}

// per-lane partial dots + 3-shfl butterfly transpose-reduce over the 4-lane group
__device__ __forceinline__ float gate_reduce(float4 x,
    const float4 &w0, const float4 &w1, const float4 &w2, const float4 &w3,
    int dblk, float bsum)
{
  float p0 = x.x*w0.x + x.y*w0.y + x.z*w0.z + x.w*w0.w;
  float p1 = x.x*w1.x + x.y*w1.y + x.z*w1.z + x.w*w1.w;
  float p2 = x.x*w2.x + x.y*w2.y + x.z*w2.z + x.w*w2.w;
  float p3 = x.x*w3.x + x.y*w3.y + x.z*w3.z + x.w*w3.w;
  float s01 = (dblk & 1) ? p0 : p1;
  float r01 = __shfl_xor_sync(0xffffffffu, s01, 1);
  float a   = ((dblk & 1) ? p1 : p0) + r01;
  float s23 = (dblk & 1) ? p2 : p3;
  float r23 = __shfl_xor_sync(0xffffffffu, s23, 1);
  float bb  = ((dblk & 1) ? p3 : p2) + r23;
  float snd = (dblk & 2) ? a : bb;
  float rcv = __shfl_xor_sync(0xffffffffu, snd, 2);
  return ((dblk & 2) ? bb : a) + rcv + bsum;
}

// ============================================================================
// Kernel A: gate precompute (unchanged from R5 — near LTS-bound).
// ============================================================================
__global__ __launch_bounds__(512)
void gates_kernel(const float* __restrict__ X,   const float* __restrict__ Wih,
                  const float* __restrict__ bih, const float* __restrict__ bhh)
{
  const int lane = threadIdx.x & 31;
  const int wg   = (blockIdx.x * 512 + threadIdx.x) >> 5;   // 0..8191
  const int b_i  = lane >> 3;
  const int t_i  = (lane >> 2) & 1;
  const int dblk = lane & 3;

  const float4 w0 = *(const float4*)(Wih +  0 + dblk*4);
  const float4 w1 = *(const float4*)(Wih + 16 + dblk*4);
  const float4 w2 = *(const float4*)(Wih + 32 + dblk*4);
  const float4 w3 = *(const float4*)(Wih + 48 + dblk*4);
  const float bsum = bih[dblk] + bhh[dblk];

  #pragma unroll 1
  for (int rep = 0; rep < 2; rep++){
    const int b = (wg + rep*8192)*4 + b_i;
    const float4* xp = (const float4*)X + ((size_t)b*NT + t_i)*4 + dblk;
    float* sp = (float*)g_scratch + ((size_t)t_i*NB + b)*4 + dblk;

    #pragma unroll 1
    for (int t0 = 0; t0 < 96; t0 += 8){
      float4 xv[4];
      xv[0] = __ldg(xp);
      xv[1] = __ldg(xp + 8);
      xv[2] = __ldg(xp + 16);
      xv[3] = __ldg(xp + 24);
      xp += 32;
      #pragma unroll
      for (int q = 0; q < 4; q++){
        float gv = gate_reduce(xv[q], w0, w1, w2, w3, dblk, bsum);
        sp[(size_t)(2*q)*NB*4] = gv;
      }
      sp += (size_t)8*NB*4;
    }
    {
      float4 xa = __ldg(xp), xb = __ldg(xp + 8);
      float ga = gate_reduce(xa, w0, w1, w2, w3, dblk, bsum);
      float gb = gate_reduce(xb, w0, w1, w2, w3, dblk, bsum);
      sp[0] = ga;
      sp[(size_t)2*NB*4] = gb;
    }
  }
}

// ============================================================================
// Kernel B: phased scan + register-tiled GEMVs.
// smem (floats):
//   region A [0, 9040):  s_w1[100*64] + hr_buf[20*132]   (scan/GEMV-1 phases)
//                        overlaid by y1buf[64*132=8448]   (epilogue)
//   region B [9040, 13136): s_w2 transposed [j*64 + k]
// total 13136 floats = 52544 B -> 4 blocks/SM.
// ============================================================================
#define SM_W1 0
#define SM_HR 6400
#define SM_Y1 0
#define SM_W2 9040
#define SMB_FLOATS 13136

__global__ __launch_bounds__(128, 4)
void scan_kernel(const float* __restrict__ Whh, const float* __restrict__ W1,
                 const float* __restrict__ b1,  const float* __restrict__ W2,
                 const float* __restrict__ b2,  const float* __restrict__ W3,
                 const float* __restrict__ b3,  float* __restrict__ out)
{
  extern __shared__ float sm[];
  const int tid = threadIdx.x;
  const int b   = blockIdx.x * 128 + tid;
  const int bg  = tid >> 3;     // 0..15 : batch-group (8 batches)
  const int jg  = tid & 7;      // 0..7  : output-group (8 j / 8 k)

  for (int i = tid; i < 6400; i += 128){      // s_w1[t*64+j] = W1[j][t]
    int t = i % 100, j = i / 100;
    sm[SM_W1 + t*64 + j] = W1[i];
  }
  for (int i = tid; i < 4096; i += 128){      // s_w2[j*64+k] = W2[k][j]
    int k = i >> 6, j = i & 63;
    sm[SM_W2 + j*64 + k] = W2[i];
  }

  const float whh0 = Whh[0], whh1 = Whh[1], whh2 = Whh[2], whh3 = Whh[3];
  float h = 0.f, c = 0.f;
  unsigned long long acc[32];                 // y1 tile: acc[bb*4 + jp]
  #pragma unroll
  for (int i = 0; i < 32; i++) acc[i] = 0ull;

  __syncthreads();

  const float4* gp = g_scratch + b;
  float4 gq[4];
  gq[0] = __ldg(gp); gq[1] = __ldg(gp + NB);
  gq[2] = __ldg(gp + 2*NB); gq[3] = __ldg(gp + 3*NB);
  gp += 4*NB;

  #pragma unroll 1
  for (int c0 = 0; c0 < NT; c0 += CH){
    // ---- scan phase: 20 steps, store relu(h) to hr_buf ----
    #pragma unroll 1
    for (int s0 = 0; s0 < CH; s0 += 4){
      float4 gn[4];
      const bool more = (c0 + s0 + 4 < NT);
      if (more){
        gn[0] = __ldg(gp); gn[1] = __ldg(gp + NB);
        gn[2] = __ldg(gp + 2*NB); gn[3] = __ldg(gp + 3*NB);
        gp += 4*NB;
      }
      #pragma unroll
      for (int s = 0; s < 4; s++){
        float4 g4 = gq[s];
        float gi = sigm(g4.x + h*whh0);
        float gf = sigm(g4.y + h*whh1);
        float gg = tanh_acc(g4.z + h*whh2);
        float go = sigm(g4.w + h*whh3);
        c = gf*c + gi*gg;
        h = go * tanh_acc(c);
        sm[SM_HR + (s0 + s)*HRS + tid] = fmaxf(h, 0.f);
      }
      if (more){
        #pragma unroll
        for (int q = 0; q < 4; q++) gq[q] = gn[q];
      }
    }
    __syncthreads();

    // ---- GEMV-1 phase: 8 batches x 8 outputs register tile ----
    const float* wrow = sm + SM_W1 + c0*64 + jg*8;
    const float* hrow = sm + SM_HR + bg*8;
    #pragma unroll 2
    for (int s = 0; s < CH; s++){
      ulonglong2 w01 = *(const ulonglong2*)(wrow);       // j pairs 0,1
      ulonglong2 w23 = *(const ulonglong2*)(wrow + 4);   // j pairs 2,3
      float4 ha = *(const float4*)(hrow);
      float4 hb = *(const float4*)(hrow + 4);
      wrow += 64; hrow += HRS;
      float hv[8] = {ha.x, ha.y, ha.z, ha.w, hb.x, hb.y, hb.z, hb.w};
      #pragma unroll
      for (int bb = 0; bb < 8; bb++){
        unsigned long long hp = pack2(hv[bb], hv[bb]);
        fma2(acc[bb*4 + 0], hp, w01.x);
        fma2(acc[bb*4 + 1], hp, w01.y);
        fma2(acc[bb*4 + 2], hp, w23.x);
        fma2(acc[bb*4 + 3], hp, w23.y);
      }
    }
    __syncthreads();   // guards hr_buf reuse by next chunk (and region-A overlay)
  }

  // ==== epilogue: y1 tile -> smem [j][b] with bias+relu (overlay region A) ====
  float4 b1a = __ldg((const float4*)b1 + jg*2);
  float4 b1b = __ldg((const float4*)b1 + jg*2 + 1);
  const float bias1[8] = {b1a.x, b1a.y, b1a.z, b1a.w, b1b.x, b1b.y, b1b.z, b1b.w};

  #pragma unroll
  for (int jp = 0; jp < 4; jp++){
    float a0[8], a1[8];
    #pragma unroll
    for (int bb = 0; bb < 8; bb++){
      unpack2(acc[bb*4 + jp], a0[bb], a1[bb]);
      a0[bb] = fmaxf(a0[bb] + bias1[2*jp],     0.f);
      a1[bb] = fmaxf(a1[bb] + bias1[2*jp + 1], 0.f);
    }
    float* r0 = sm + SM_Y1 + (jg*8 + 2*jp    )*Y1S + bg*8;
    float* r1 = sm + SM_Y1 + (jg*8 + 2*jp + 1)*Y1S + bg*8;
    *(float4*)(r0)     = make_float4(a0[0], a0[1], a0[2], a0[3]);
    *(float4*)(r0 + 4) = make_float4(a0[4], a0[5], a0[6], a0[7]);
    *(float4*)(r1)     = make_float4(a1[0], a1[1], a1[2], a1[3]);
    *(float4*)(r1 + 4) = make_float4(a1[4], a1[5], a1[6], a1[7]);
  }
  __syncthreads();

  // ==== GEMV-2: layer 2, 8 batches x 8 k register tile ====
  unsigned long long zacc[32];               // zacc[bb*4 + kp]
  #pragma unroll
  for (int i = 0; i < 32; i++) zacc[i] = 0ull;

  {
    const float* arow = sm + SM_Y1 + bg*8;
    const float* w2p  = sm + SM_W2 + jg*8;   // kg == jg
    #pragma unroll 2
    for (int j = 0; j < 64; j++){
      ulonglong2 w01 = *(const ulonglong2*)(w2p);
      ulonglong2 w23 = *(const ulonglong2*)(w2p + 4);
      float4 aa = *(const float4*)(arow);
      float4 ab = *(const float4*)(arow + 4);
      w2p += 64; arow += Y1S;
      float av[8] = {aa.x, aa.y, aa.z, aa.w, ab.x, ab.y, ab.z, ab.w};
      #pragma unroll
      for (int bb = 0; bb < 8; bb++){
        unsigned long long ap = pack2(av[bb], av[bb]);
        fma2(zacc[bb*4 + 0], ap, w01.x);
        fma2(zacc[bb*4 + 1], ap, w01.y);
        fma2(zacc[bb*4 + 2], ap, w23.x);
        fma2(zacc[bb*4 + 3], ap, w23.y);
      }
    }
  }

  // ==== layer 3 partials + butterfly reduce over the 8 kg lanes ====
  float4 b2a  = __ldg((const float4*)b2 + jg*2);
  float4 b2b  = __ldg((const float4*)b2 + jg*2 + 1);
  float4 w30a = __ldg((const float4*)W3 + jg*2);
  float4 w30b = __ldg((const float4*)W3 + jg*2 + 1);
  float4 w31a = __ldg((const float4*)(W3 + 64) + jg*2);
  float4 w31b = __ldg((const float4*)(W3 + 64) + jg*2 + 1);
  const float bias2[8] = {b2a.x, b2a.y, b2a.z, b2a.w, b2b.x, b2b.y, b2b.z, b2b.w};
  const float w30[8]   = {w30a.x, w30a.y, w30a.z, w30a.w, w30b.x, w30b.y, w30b.z, w30b.w};
  const float w31[8]   = {w31a.x, w31a.y, w31a.z, w31a.w, w31b.x, w31b.y, w31b.z, w31b.w};

  float y0p[8], y1p[8];
  #pragma unroll
  for (int bb = 0; bb < 8; bb++){
    float s0 = 0.f, s1 = 0.f;
    #pragma unroll
    for (int kp = 0; kp < 4; kp++){
      float z0, z1; unpack2(zacc[bb*4 + kp], z0, z1);
      z0 = fmaxf(z0 + bias2[2*kp],     0.f);
      z1 = fmaxf(z1 + bias2[2*kp + 1], 0.f);
      s0 += z0*w30[2*kp] + z1*w30[2*kp + 1];
      s1 += z0*w31[2*kp] + z1*w31[2*kp + 1];
    }
    y0p[bb] = s0; y1p[bb] = s1;
  }
  #pragma unroll
  for (int m = 1; m <= 4; m <<= 1){
    #pragma unroll
    for (int bb = 0; bb < 8; bb++){
      y0p[bb] += __shfl_xor_sync(0xffffffffu, y0p[bb], m);
      y1p[bb] += __shfl_xor_sync(0xffffffffu, y1p[bb], m);
    }
  }
  // lane (bg, jg) owns batch bg*8 + jg == tid after the full butterfly
  float y0 = y0p[jg] + __ldg(b3);
  float y1 = y1p[jg] + __ldg(b3 + 1);
  float mm  = fmaxf(y0, y1);
  float lse = mm + __logf(__expf(y0 - mm) + __expf(y1 - mm));
  ((float2*)out)[b] = make_float2(y0 - lse, y1 - lse);
}

extern "C" void kernel_launch(void* const* d_in, const int* in_sizes, int n_in,
                              void* d_out, int out_size)
{
  const float* X   = (const float*)d_in[0];
  const float* Wih = (const float*)d_in[1];
  const float* Whh = (const float*)d_in[2];
  const float* bih = (const float*)d_in[3];
  const float* bhh = (const float*)d_in[4];
  const float* W1  = (const float*)d_in[5];
  const float* b1  = (const float*)d_in[6];
  const float* W2  = (const float*)d_in[7];
  const float* b2  = (const float*)d_in[8];
  const float* W3  = (const float*)d_in[9];
  const float* b3  = (const float*)d_in[10];

  gates_kernel<<<512, 512>>>(X, Wih, bih, bhh);

  const size_t smem = SMB_FLOATS * sizeof(float);   // 52544 B
  cudaFuncSetAttribute(scan_kernel, cudaFuncAttributeMaxDynamicSharedMemorySize, (int)smem);
  scan_kernel<<<NB / 128, 128, smem>>>(Whh, W1, b1, W2, b2, W3, b3, (float*)d_out);
}

// round 7
// speedup vs baseline: 2.8484x; 1.0550x over previous
#include <cuda_runtime.h>
#include <cuda_fp16.h>

#define NB 65536
#define NT 100
#define CH 20            // scan steps per chunk
#define HRS 128          // hr_buf row stride (floats)
#define Y1S 132          // y1buf row stride (floats)

// 52 MB fp16 gate scratch: per (t,b) one uint2 = {half2(g0,g1), half2(g2,g3)}
__device__ uint2 g_scratch16[(size_t)NB * NT];

// ---- activations ----
__device__ __forceinline__ float sigm(float x){
  return __fdividef(1.f, 1.f + __expf(-x));
}
__device__ __forceinline__ float tanh_acc(float x){
  return 1.f - __fdividef(2.f, __expf(2.f*x) + 1.f);
}

// ---- packed f32x2 helpers ----
__device__ __forceinline__ void fma2(unsigned long long &d, unsigned long long a, unsigned long long b){
  asm("fma.rn.f32x2 %0, %1, %2, %0;" : "+l"(d) : "l"(a), "l"(b));
}
__device__ __forceinline__ unsigned long long pack2(float lo, float hi){
  unsigned long long r; asm("mov.b64 %0, {%1,%2};" : "=l"(r) : "f"(lo), "f"(hi)); return r;
}
__device__ __forceinline__ void unpack2(unsigned long long v, float &lo, float &hi){
  asm("mov.b64 {%0,%1}, %2;" : "=f"(lo), "=f"(hi) : "l"(v));
}

// per-lane partial dots + 3-shfl butterfly transpose-reduce over the 4-lane group
__device__ __forceinline__ float gate_reduce(float4 x,
    const float4 &w0, const float4 &w1, const float4 &w2, const float4 &w3,
    int dblk, float bsum)
{
  float p0 = x.x*w0.x + x.y*w0.y + x.z*w0.z + x.w*w0.w;
  float p1 = x.x*w1.x + x.y*w1.y + x.z*w1.z + x.w*w1.w;
  float p2 = x.x*w2.x + x.y*w2.y + x.z*w2.z + x.w*w2.w;
  float p3 = x.x*w3.x + x.y*w3.y + x.z*w3.z + x.w*w3.w;
  float s01 = (dblk & 1) ? p0 : p1;
  float r01 = __shfl_xor_sync(0xffffffffu, s01, 1);
  float a   = ((dblk & 1) ? p1 : p0) + r01;
  float s23 = (dblk & 1) ? p2 : p3;
  float r23 = __shfl_xor_sync(0xffffffffu, s23, 1);
  float bb  = ((dblk & 1) ? p3 : p2) + r23;
  float snd = (dblk & 2) ? a : bb;
  float rcv = __shfl_xor_sync(0xffffffffu, snd, 2);
  return ((dblk & 2) ? bb : a) + rcv + bsum;
}

// pair (g0,g1)/(g2,g3) across lanes and store half2 packs from even-dblk lanes
__device__ __forceinline__ void store_gate_h2(unsigned* sp, float gv, int dblk){
  float ghi = __shfl_xor_sync(0xffffffffu, gv, 1);
  if (!(dblk & 1)){
    __half2 hh = __floats2half2_rn(gv, ghi);
    *sp = *(const unsigned*)&hh;
  }
}

// ============================================================================
// Kernel A: gate precompute -> fp16 scratch. Warp tile = 4 batches x 2 t per
// store set, 8 timesteps per loop iter (4 independent LDG.128).
// ============================================================================
__global__ __launch_bounds__(512)
void gates_kernel(const float* __restrict__ X,   const float* __restrict__ Wih,
                  const float* __restrict__ bih, const float* __restrict__ bhh)
{
  const int lane = threadIdx.x & 31;
  const int wg   = (blockIdx.x * 512 + threadIdx.x) >> 5;   // 0..8191
  const int b_i  = lane >> 3;
  const int t_i  = (lane >> 2) & 1;
  const int dblk = lane & 3;

  const float4 w0 = *(const float4*)(Wih +  0 + dblk*4);
  const float4 w1 = *(const float4*)(Wih + 16 + dblk*4);
  const float4 w2 = *(const float4*)(Wih + 32 + dblk*4);
  const float4 w3 = *(const float4*)(Wih + 48 + dblk*4);
  const float bsum = bih[dblk] + bhh[dblk];

  #pragma unroll 1
  for (int rep = 0; rep < 2; rep++){
    const int b = (wg + rep*8192)*4 + b_i;
    const float4* xp = (const float4*)X + ((size_t)b*NT + t_i)*4 + dblk;
    // scratch as unsigned: per (t,b) two uints; this lane writes slot dblk>>1
    unsigned* sp = (unsigned*)g_scratch16 + ((size_t)t_i*NB + b)*2 + (dblk >> 1);

    #pragma unroll 1
    for (int t0 = 0; t0 < 96; t0 += 8){
      float4 xv[4];
      xv[0] = __ldg(xp);
      xv[1] = __ldg(xp + 8);
      xv[2] = __ldg(xp + 16);
      xv[3] = __ldg(xp + 24);
      xp += 32;
      #pragma unroll
      for (int q = 0; q < 4; q++){
        float gv = gate_reduce(xv[q], w0, w1, w2, w3, dblk, bsum);
        store_gate_h2(sp + (size_t)(2*q)*NB*2, gv, dblk);
      }
      sp += (size_t)8*NB*2;
    }
    {   // tail t0 = 96..99
      float4 xa = __ldg(xp), xb = __ldg(xp + 8);
      float ga = gate_reduce(xa, w0, w1, w2, w3, dblk, bsum);
      float gb = gate_reduce(xb, w0, w1, w2, w3, dblk, bsum);
      store_gate_h2(sp, ga, dblk);
      store_gate_h2(sp + (size_t)2*NB*2, gb, dblk);
    }
  }
}

// ============================================================================
// Kernel B: phased scan + register-tiled GEMVs, deep register gate prefetch.
// smem (floats):
//   region A [0, 8960):  s_w1[6400] + hr_buf[20*128=2560]  (scan/GEMV-1)
//                        overlaid by y1buf[64*132=8448]     (epilogue)
//   region B [8960, 13056): s_w2 transposed [j*64 + k]
// total 13056 floats = 52224 B -> 4 blocks/SM.
// ============================================================================
#define SM_W1 0
#define SM_HR 6400
#define SM_Y1 0
#define SM_W2 8960
#define SMB_FLOATS 13056

__global__ __launch_bounds__(128, 4)
void scan_kernel(const float* __restrict__ Whh, const float* __restrict__ W1,
                 const float* __restrict__ b1,  const float* __restrict__ W2,
                 const float* __restrict__ b2,  const float* __restrict__ W3,
                 const float* __restrict__ b3,  float* __restrict__ out)
{
  extern __shared__ float sm[];
  const int tid = threadIdx.x;
  const int b   = blockIdx.x * 128 + tid;
  const int bg  = tid >> 3;     // 0..15 : batch-group (8 batches)
  const int jg  = tid & 7;      // 0..7  : output-group (8 j / 8 k)

  const uint2* gbase = g_scratch16 + b;

  // issue first half-chunk of gate loads ASAP (MLP=10, hidden under staging)
  uint2 gc1[10], gc2[10];
  #pragma unroll
  for (int i = 0; i < 10; i++) gc1[i] = __ldg(gbase + (size_t)i*NB);

  for (int i = tid; i < 6400; i += 128){      // s_w1[t*64+j] = W1[j][t]
    int t = i % 100, j = i / 100;
    sm[SM_W1 + t*64 + j] = W1[i];
  }
  for (int i = tid; i < 4096; i += 128){      // s_w2[j*64+k] = W2[k][j]
    int k = i >> 6, j = i & 63;
    sm[SM_W2 + j*64 + k] = W2[i];
  }

  const float whh0 = Whh[0], whh1 = Whh[1], whh2 = Whh[2], whh3 = Whh[3];
  float h = 0.f, c = 0.f;
  unsigned long long acc[32];                 // y1 tile: acc[bb*4 + jp]
  #pragma unroll
  for (int i = 0; i < 32; i++) acc[i] = 0ull;

  __syncthreads();

  #pragma unroll 1
  for (int cidx = 0; cidx < 5; cidx++){
    const int c0 = cidx * CH;

    // ---- scan phase: 20 steps; second half-chunk loads issued at step 4 ----
    #pragma unroll
    for (int s = 0; s < CH; s++){
      if (s == 4){
        const uint2* p2 = gbase + (size_t)(c0 + 10)*NB;
        #pragma unroll
        for (int i = 0; i < 10; i++) gc2[i] = __ldg(p2 + (size_t)i*NB);
      }
      uint2 u = (s < 10) ? gc1[s] : gc2[s - 10];
      float2 glo = __half22float2(*(const __half2*)&u.x);   // (g0, g1)
      float2 ghi = __half22float2(*(const __half2*)&u.y);   // (g2, g3)
      float gi = sigm(glo.x + h*whh0);
      float gf = sigm(glo.y + h*whh1);
      float gg = tanh_acc(ghi.x + h*whh2);
      float go = sigm(ghi.y + h*whh3);
      c = gf*c + gi*gg;
      h = go * tanh_acc(c);
      sm[SM_HR + s*HRS + tid] = fmaxf(h, 0.f);
    }
    __syncthreads();

    // prefetch next chunk's first half; GEMV-1 (~1300 cyc) hides it fully
    if (cidx < 4){
      const uint2* p1 = gbase + (size_t)(c0 + CH)*NB;
      #pragma unroll
      for (int i = 0; i < 10; i++) gc1[i] = __ldg(p1 + (size_t)i*NB);
    }

    // ---- GEMV-1 phase: 8 batches x 8 outputs register tile ----
    const float* wrow = sm + SM_W1 + c0*64 + jg*8;
    const float* hrow = sm + SM_HR + bg*8;
    #pragma unroll 2
    for (int s = 0; s < CH; s++){
      ulonglong2 w01 = *(const ulonglong2*)(wrow);       // j pairs 0,1
      ulonglong2 w23 = *(const ulonglong2*)(wrow + 4);   // j pairs 2,3
      float4 ha = *(const float4*)(hrow);
      float4 hb = *(const float4*)(hrow + 4);
      wrow += 64; hrow += HRS;
      float hv[8] = {ha.x, ha.y, ha.z, ha.w, hb.x, hb.y, hb.z, hb.w};
      #pragma unroll
      for (int bb = 0; bb < 8; bb++){
        unsigned long long hp = pack2(hv[bb], hv[bb]);
        fma2(acc[bb*4 + 0], hp, w01.x);
        fma2(acc[bb*4 + 1], hp, w01.y);
        fma2(acc[bb*4 + 2], hp, w23.x);
        fma2(acc[bb*4 + 3], hp, w23.y);
      }
    }
    __syncthreads();   // hr_buf / region-A reuse guard
  }

  // ==== epilogue: y1 tile -> smem [j][b] with bias+relu (overlay region A) ====
  float4 b1a = __ldg((const float4*)b1 + jg*2);
  float4 b1b = __ldg((const float4*)b1 + jg*2 + 1);
  const float bias1[8] = {b1a.x, b1a.y, b1a.z, b1a.w, b1b.x, b1b.y, b1b.z, b1b.w};

  #pragma unroll
  for (int jp = 0; jp < 4; jp++){
    float a0[8], a1[8];
    #pragma unroll
    for (int bb = 0; bb < 8; bb++){
      unpack2(acc[bb*4 + jp], a0[bb], a1[bb]);
      a0[bb] = fmaxf(a0[bb] + bias1[2*jp],     0.f);
      a1[bb] = fmaxf(a1[bb] + bias1[2*jp + 1], 0.f);
    }
    float* r0 = sm + SM_Y1 + (jg*8 + 2*jp    )*Y1S + bg*8;
    float* r1 = sm + SM_Y1 + (jg*8 + 2*jp + 1)*Y1S + bg*8;
    *(float4*)(r0)     = make_float4(a0[0], a0[1], a0[2], a0[3]);
    *(float4*)(r0 + 4) = make_float4(a0[4], a0[5], a0[6], a0[7]);
    *(float4*)(r1)     = make_float4(a1[0], a1[1], a1[2], a1[3]);
    *(float4*)(r1 + 4) = make_float4(a1[4], a1[5], a1[6], a1[7]);
  }
  __syncthreads();

  // ==== GEMV-2: layer 2, 8 batches x 8 k register tile ====
  unsigned long long zacc[32];               // zacc[bb*4 + kp]
  #pragma unroll
  for (int i = 0; i < 32; i++) zacc[i] = 0ull;

  {
    const float* arow = sm + SM_Y1 + bg*8;
    const float* w2p  = sm + SM_W2 + jg*8;   // kg == jg
    #pragma unroll 2
    for (int j = 0; j < 64; j++){
      ulonglong2 w01 = *(const ulonglong2*)(w2p);
      ulonglong2 w23 = *(const ulonglong2*)(w2p + 4);
      float4 aa = *(const float4*)(arow);
      float4 ab = *(const float4*)(arow + 4);
      w2p += 64; arow += Y1S;
      float av[8] = {aa.x, aa.y, aa.z, aa.w, ab.x, ab.y, ab.z, ab.w};
      #pragma unroll
      for (int bb = 0; bb < 8; bb++){
        unsigned long long ap = pack2(av[bb], av[bb]);
        fma2(zacc[bb*4 + 0], ap, w01.x);
        fma2(zacc[bb*4 + 1], ap, w01.y);
        fma2(zacc[bb*4 + 2], ap, w23.x);
        fma2(zacc[bb*4 + 3], ap, w23.y);
      }
    }
  }

  // ==== layer 3 partials + butterfly reduce over the 8 kg lanes ====
  float4 b2a  = __ldg((const float4*)b2 + jg*2);
  float4 b2b  = __ldg((const float4*)b2 + jg*2 + 1);
  float4 w30a = __ldg((const float4*)W3 + jg*2);
  float4 w30b = __ldg((const float4*)W3 + jg*2 + 1);
  float4 w31a = __ldg((const float4*)(W3 + 64) + jg*2);
  float4 w31b = __ldg((const float4*)(W3 + 64) + jg*2 + 1);
  const float bias2[8] = {b2a.x, b2a.y, b2a.z, b2a.w, b2b.x, b2b.y, b2b.z, b2b.w};
  const float w30[8]   = {w30a.x, w30a.y, w30a.z, w30a.w, w30b.x, w30b.y, w30b.z, w30b.w};
  const float w31[8]   = {w31a.x, w31a.y, w31a.z, w31a.w, w31b.x, w31b.y, w31b.z, w31b.w};

  float y0p[8], y1p[8];
  #pragma unroll
  for (int bb = 0; bb < 8; bb++){
    float s0 = 0.f, s1 = 0.f;
    #pragma unroll
    for (int kp = 0; kp < 4; kp++){
      float z0, z1; unpack2(zacc[bb*4 + kp], z0, z1);
      z0 = fmaxf(z0 + bias2[2*kp],     0.f);
      z1 = fmaxf(z1 + bias2[2*kp + 1], 0.f);
      s0 += z0*w30[2*kp] + z1*w30[2*kp + 1];
      s1 += z0*w31[2*kp] + z1*w31[2*kp + 1];
    }
    y0p[bb] = s0; y1p[bb] = s1;
  }
  #pragma unroll
  for (int m = 1; m <= 4; m <<= 1){
    #pragma unroll
    for (int bb = 0; bb < 8; bb++){
      y0p[bb] += __shfl_xor_sync(0xffffffffu, y0p[bb], m);
      y1p[bb] += __shfl_xor_sync(0xffffffffu, y1p[bb], m);
    }
  }
  // lane (bg, jg) owns batch bg*8 + jg == tid after the full butterfly
  float y0 = y0p[jg] + __ldg(b3);
  float y1 = y1p[jg] + __ldg(b3 + 1);
  float mm  = fmaxf(y0, y1);
  float lse = mm + __logf(__expf(y0 - mm) + __expf(y1 - mm));
  ((float2*)out)[b] = make_float2(y0 - lse, y1 - lse);
}

extern "C" void kernel_launch(void* const* d_in, const int* in_sizes, int n_in,
                              void* d_out, int out_size)
{
  const float* X   = (const float*)d_in[0];
  const float* Wih = (const float*)d_in[1];
  const float* Whh = (const float*)d_in[2];
  const float* bih = (const float*)d_in[3];
  const float* bhh = (const float*)d_in[4];
  const float* W1  = (const float*)d_in[5];
  const float* b1  = (const float*)d_in[6];
  const float* W2  = (const float*)d_in[7];
  const float* b2  = (const float*)d_in[8];
  const float* W3  = (const float*)d_in[9];
  const float* b3  = (const float*)d_in[10];

  gates_kernel<<<512, 512>>>(X, Wih, bih, bhh);

  const size_t smem = SMB_FLOATS * sizeof(float);   // 52224 B
  cudaFuncSetAttribute(scan_kernel, cudaFuncAttributeMaxDynamicSharedMemorySize, (int)smem);
  scan_kernel<<<NB / 128, 128, smem>>>(Whh, W1, b1, W2, b2, W3, b3, (float*)d_out);
}

// round 9
// speedup vs baseline: 3.8089x; 1.3372x over previous
#include <cuda_runtime.h>
#include <cuda_fp16.h>
#include <cstdint>

#define NB 65536
#define NT 100

// 52 MB fp16 gate scratch: per (t,b) one uint2 = {half2(g0,g1), half2(g2,g3)}
__device__ uint2 g_scratch16[(size_t)NB * NT];

// ---- activations ----
__device__ __forceinline__ float sigm(float x){
  return __fdividef(1.f, 1.f + __expf(-x));
}
__device__ __forceinline__ float tanh_acc(float x){
  return 1.f - __fdividef(2.f, __expf(2.f*x) + 1.f);
}

// per-lane partial dots + 3-shfl butterfly transpose-reduce over the 4-lane group
__device__ __forceinline__ float gate_reduce(float4 x,
    const float4 &w0, const float4 &w1, const float4 &w2, const float4 &w3,
    int dblk, float bsum)
{
  float p0 = x.x*w0.x + x.y*w0.y + x.z*w0.z + x.w*w0.w;
  float p1 = x.x*w1.x + x.y*w1.y + x.z*w1.z + x.w*w1.w;
  float p2 = x.x*w2.x + x.y*w2.y + x.z*w2.z + x.w*w2.w;
  float p3 = x.x*w3.x + x.y*w3.y + x.z*w3.z + x.w*w3.w;
  float s01 = (dblk & 1) ? p0 : p1;
  float r01 = __shfl_xor_sync(0xffffffffu, s01, 1);
  float a   = ((dblk & 1) ? p1 : p0) + r01;
  float s23 = (dblk & 1) ? p2 : p3;
  float r23 = __shfl_xor_sync(0xffffffffu, s23, 1);
  float bb  = ((dblk & 1) ? p3 : p2) + r23;
  float snd = (dblk & 2) ? a : bb;
  float rcv = __shfl_xor_sync(0xffffffffu, snd, 2);
  return ((dblk & 2) ? bb : a) + rcv + bsum;
}

__device__ __forceinline__ void store_gate_h2(unsigned* sp, float gv, int dblk){
  float ghi = __shfl_xor_sync(0xffffffffu, gv, 1);
  if (!(dblk & 1)){
    __half2 hh = __floats2half2_rn(gv, ghi);
    *sp = *(const unsigned*)&hh;
  }
}

// ============================================================================
// Kernel A: gate precompute -> fp16 scratch (unchanged from R7).
// ============================================================================
__global__ __launch_bounds__(512)
void gates_kernel(const float* __restrict__ X,   const float* __restrict__ Wih,
                  const float* __restrict__ bih, const float* __restrict__ bhh)
{
  const int lane = threadIdx.x & 31;
  const int wg   = (blockIdx.x * 512 + threadIdx.x) >> 5;
  const int b_i  = lane >> 3;
  const int t_i  = (lane >> 2) & 1;
  const int dblk = lane & 3;

  const float4 w0 = *(const float4*)(Wih +  0 + dblk*4);
  const float4 w1 = *(const float4*)(Wih + 16 + dblk*4);
  const float4 w2 = *(const float4*)(Wih + 32 + dblk*4);
  const float4 w3 = *(const float4*)(Wih + 48 + dblk*4);
  const float bsum = bih[dblk] + bhh[dblk];

  #pragma unroll 1
  for (int rep = 0; rep < 2; rep++){
    const int b = (wg + rep*8192)*4 + b_i;
    const float4* xp = (const float4*)X + ((size_t)b*NT + t_i)*4 + dblk;
    unsigned* sp = (unsigned*)g_scratch16 + ((size_t)t_i*NB + b)*2 + (dblk >> 1);

    #pragma unroll 1
    for (int t0 = 0; t0 < 96; t0 += 8){
      float4 xv[4];
      xv[0] = __ldg(xp);
      xv[1] = __ldg(xp + 8);
      xv[2] = __ldg(xp + 16);
      xv[3] = __ldg(xp + 24);
      xp += 32;
      #pragma unroll
      for (int q = 0; q < 4; q++){
        float gv = gate_reduce(xv[q], w0, w1, w2, w3, dblk, bsum);
        store_gate_h2(sp + (size_t)(2*q)*NB*2, gv, dblk);
      }
      sp += (size_t)8*NB*2;
    }
    {
      float4 xa = __ldg(xp), xb = __ldg(xp + 8);
      float ga = gate_reduce(xa, w0, w1, w2, w3, dblk, bsum);
      float gb = gate_reduce(xb, w0, w1, w2, w3, dblk, bsum);
      store_gate_h2(sp, ga, dblk);
      store_gate_h2(sp + (size_t)2*NB*2, gb, dblk);
    }
  }
}

// ============================================================================
// Kernel B: LSTM scan + HMMA (mma.sync m16n8k16) for both dense layers.
// smem layout (bytes), pitch 240 B (= 120 halves; 60 mod 32 walk -> ldmatrix
// and STS.128 both conflict-free):
//   A [0, 30720)     : hr fp16 [128 rows][K=112+pad], row-major;
//                      later overlaid (cols 0..63) by A2 = relu(y1) fp16
//   B [30720, 46080) : W1 fp16 [64 n][112+pad k]; later overlaid by W2 [64][64]
// total 46080 B -> 4 blocks/SM.
// ============================================================================
#define SMEM_A 0
#define SMEM_B 30720
#define SMEM_TOT 46080
#define PITCH 240

static __device__ __forceinline__ uint32_t smem_u32(const void* p){
  uint32_t a;
  asm("{ .reg .u64 t; cvta.to.shared.u64 t, %1; cvt.u32.u64 %0, t; }" : "=r"(a) : "l"(p));
  return a;
}
__device__ __forceinline__ void ldsm_x4(uint32_t* r, uint32_t addr){
  asm volatile("ldmatrix.sync.aligned.m8n8.x4.shared.b16 {%0,%1,%2,%3}, [%4];"
    : "=r"(r[0]),"=r"(r[1]),"=r"(r[2]),"=r"(r[3]) : "r"(addr));
}
__device__ __forceinline__ void ldsm_x2(uint32_t* r, uint32_t addr){
  asm volatile("ldmatrix.sync.aligned.m8n8.x2.shared.b16 {%0,%1}, [%2];"
    : "=r"(r[0]),"=r"(r[1]) : "r"(addr));
}
__device__ __forceinline__ void mma16816(float* c, const uint32_t* a, const uint32_t* b){
  asm volatile("mma.sync.aligned.m16n8k16.row.col.f32.f16.f16.f32 "
    "{%0,%1,%2,%3}, {%4,%5,%6,%7}, {%8,%9}, {%0,%1,%2,%3};"
    : "+f"(c[0]),"+f"(c[1]),"+f"(c[2]),"+f"(c[3])
    : "r"(a[0]),"r"(a[1]),"r"(a[2]),"r"(a[3]), "r"(b[0]),"r"(b[1]));
}

__global__ __launch_bounds__(128, 4)
void scan_kernel(const float* __restrict__ Whh, const float* __restrict__ W1,
                 const float* __restrict__ b1,  const float* __restrict__ W2,
                 const float* __restrict__ b2,  const float* __restrict__ W3,
                 const float* __restrict__ b3,  float* __restrict__ out)
{
  extern __shared__ char smem[];
  const int tid  = threadIdx.x;
  const int wid  = tid >> 5;
  const int lane = tid & 31;
  const int b    = blockIdx.x * 128 + tid;
  const uint32_t sbase = smem_u32(smem);

  // issue first gate block ASAP
  const uint2* gbase = g_scratch16 + b;
  uint2 gA[8], gB[8];
  #pragma unroll
  for (int i = 0; i < 8; i++) gA[i] = __ldg(gbase + (size_t)i*NB);

  // zero A + B regions (covers all K zero-padding)
  {
    uint4 z4 = make_uint4(0,0,0,0);
    uint4* zp = (uint4*)smem;
    for (int i = tid; i < SMEM_TOT/16; i += 128) zp[i] = z4;
  }
  __syncthreads();

  // stage W1 -> B as [n=j][k=t] fp16 (native .col layout for B operand)
  {
    __half* sB = (__half*)(smem + SMEM_B);
    for (int i = tid; i < 6400; i += 128){
      int j = i / 100, t = i % 100;
      sB[j*120 + t] = __float2half(W1[i]);
    }
  }

  // ---- LSTM scan: 100 steps, relu(h) fp16 -> A[row=tid][t] ----
  const float whh0 = Whh[0], whh1 = Whh[1], whh2 = Whh[2], whh3 = Whh[3];
  char* arow = smem + SMEM_A + tid*PITCH;
  float h = 0.f, c = 0.f;
  float hv[8];

  #pragma unroll 1
  for (int grp = 0; grp < 12; grp++){
    #pragma unroll
    for (int sl = 0; sl < 8; sl++){
      if (sl == 2){   // prefetch next 8 steps (or 4-step tail) into alt buffer
        const uint2* pn = gbase + (size_t)(grp*8 + 8)*NB;
        const int nld = (grp < 11) ? 8 : 4;
        #pragma unroll
        for (int i = 0; i < 8; i++){
          if (i < nld){
            uint2 v = __ldg(pn + (size_t)i*NB);
            if (grp & 1) gA[i] = v; else gB[i] = v;
          }
        }
      }
      uint2 u = (grp & 1) ? gB[sl] : gA[sl];
      float2 glo = __half22float2(*(const __half2*)&u.x);
      float2 ghi = __half22float2(*(const __half2*)&u.y);
      float gi = sigm(glo.x + h*whh0);
      float gf = sigm(glo.y + h*whh1);
      float gg = tanh_acc(ghi.x + h*whh2);
      float go = sigm(ghi.y + h*whh3);
      c = gf*c + gi*gg;
      h = go * tanh_acc(c);
      hv[sl] = fmaxf(h, 0.f);
    }
    __half2 p0 = __floats2half2_rn(hv[0], hv[1]);
    __half2 p1 = __floats2half2_rn(hv[2], hv[3]);
    __half2 p2 = __floats2half2_rn(hv[4], hv[5]);
    __half2 p3 = __floats2half2_rn(hv[6], hv[7]);
    *(uint4*)(arow + grp*16) =
      make_uint4(*(uint32_t*)&p0, *(uint32_t*)&p1, *(uint32_t*)&p2, *(uint32_t*)&p3);
  }
  // tail steps 96..99 (in gA, loaded during grp 11)
  #pragma unroll
  for (int sl = 0; sl < 4; sl++){
    uint2 u = gA[sl];
    float2 glo = __half22float2(*(const __half2*)&u.x);
    float2 ghi = __half22float2(*(const __half2*)&u.y);
    float gi = sigm(glo.x + h*whh0);
    float gf = sigm(glo.y + h*whh1);
    float gg = tanh_acc(ghi.x + h*whh2);
    float go = sigm(ghi.y + h*whh3);
    c = gf*c + gi*gg;
    h = go * tanh_acc(c);
    hv[sl] = fmaxf(h, 0.f);
  }
  {
    __half2 p0 = __floats2half2_rn(hv[0], hv[1]);
    __half2 p1 = __floats2half2_rn(hv[2], hv[3]);
    *(uint4*)(arow + 192) = make_uint4(*(uint32_t*)&p0, *(uint32_t*)&p1, 0u, 0u);
  }
  __syncthreads();

  // ldmatrix per-lane base addresses
  const uint32_t a_lm = sbase + SMEM_A
      + (uint32_t)(wid*32 + (lane & 7) + ((lane >> 3) & 1)*8)*PITCH
      + (uint32_t)((lane >> 4) & 1)*16;
  const uint32_t b_lm = sbase + SMEM_B
      + (uint32_t)(lane & 7)*PITCH + (uint32_t)((lane >> 3) & 1)*16;

  // ---- MMA-1: y1[128,64] = hr[128,112] @ W1^T (7 k-steps) ----
  float c1[2][8][4];
  #pragma unroll
  for (int mi = 0; mi < 2; mi++)
    #pragma unroll
    for (int ni = 0; ni < 8; ni++)
      #pragma unroll
      for (int q = 0; q < 4; q++) c1[mi][ni][q] = 0.f;

  #pragma unroll
  for (int k = 0; k < 7; k++){
    uint32_t bf[8][2];
    #pragma unroll
    for (int ni = 0; ni < 8; ni++) ldsm_x2(bf[ni], b_lm + ni*(8*PITCH) + k*32);
    #pragma unroll
    for (int mi = 0; mi < 2; mi++){
      uint32_t af[4];
      ldsm_x4(af, a_lm + mi*(16*PITCH) + k*32);
      #pragma unroll
      for (int ni = 0; ni < 8; ni++) mma16816(c1[mi][ni], af, bf[ni]);
    }
  }
  __syncthreads();   // everyone done reading A (hr) and B (W1)

  // ---- relu(y1+b1) -> A2 (cols 0..63 of A region); stage W2 -> B ----
  {
    __half* sB = (__half*)(smem + SMEM_B);
    for (int i = tid; i < 4096; i += 128){
      int ko = i >> 6, j = i & 63;
      sB[ko*120 + j] = __float2half(W2[i]);
    }
  }
  {
    const int col = (lane & 3)*2;
    const int r0  = wid*32 + (lane >> 2);
    #pragma unroll
    for (int ni = 0; ni < 8; ni++){
      int cc = ni*8 + col;
      float b1a = __ldg(b1 + cc), b1b = __ldg(b1 + cc + 1);
      #pragma unroll
      for (int mi = 0; mi < 2; mi++){
        float v0 = fmaxf(c1[mi][ni][0] + b1a, 0.f);
        float v1 = fmaxf(c1[mi][ni][1] + b1b, 0.f);
        float v2 = fmaxf(c1[mi][ni][2] + b1a, 0.f);
        float v3 = fmaxf(c1[mi][ni][3] + b1b, 0.f);
        __half2 h01 = __floats2half2_rn(v0, v1);
        __half2 h23 = __floats2half2_rn(v2, v3);
        *(uint32_t*)(smem + SMEM_A + (r0 + mi*16    )*PITCH + cc*2) = *(uint32_t*)&h01;
        *(uint32_t*)(smem + SMEM_A + (r0 + mi*16 + 8)*PITCH + cc*2) = *(uint32_t*)&h23;
      }
    }
  }
  __syncthreads();

  // ---- MMA-2: z[128,64] = a2[128,64] @ W2^T (4 k-steps) ----
  float c2[2][8][4];
  #pragma unroll
  for (int mi = 0; mi < 2; mi++)
    #pragma unroll
    for (int ni = 0; ni < 8; ni++)
      #pragma unroll
      for (int q = 0; q < 4; q++) c2[mi][ni][q] = 0.f;

  #pragma unroll
  for (int k = 0; k < 4; k++){
    uint32_t bf[8][2];
    #pragma unroll
    for (int ni = 0; ni < 8; ni++) ldsm_x2(bf[ni], b_lm + ni*(8*PITCH) + k*32);
    #pragma unroll
    for (int mi = 0; mi < 2; mi++){
      uint32_t af[4];
      ldsm_x4(af, a_lm + mi*(16*PITCH) + k*32);
      #pragma unroll
      for (int ni = 0; ni < 8; ni++) mma16816(c2[mi][ni], af, bf[ni]);
    }
  }

  // ---- layer 3 in-fragment + quad butterfly + log_softmax ----
  float yp[4][2];
  #pragma unroll
  for (int r = 0; r < 4; r++){ yp[r][0] = 0.f; yp[r][1] = 0.f; }

  {
    const int col = (lane & 3)*2;
    #pragma unroll
    for (int ni = 0; ni < 8; ni++){
      int cc = ni*8 + col;
      float b2a = __ldg(b2 + cc),      b2b = __ldg(b2 + cc + 1);
      float w00 = __ldg(W3 + cc),      w01 = __ldg(W3 + cc + 1);
      float w10 = __ldg(W3 + 64 + cc), w11 = __ldg(W3 + 64 + cc + 1);
      #pragma unroll
      for (int mi = 0; mi < 2; mi++){
        float z0 = fmaxf(c2[mi][ni][0] + b2a, 0.f);
        float z1 = fmaxf(c2[mi][ni][1] + b2b, 0.f);
        float z2 = fmaxf(c2[mi][ni][2] + b2a, 0.f);
        float z3 = fmaxf(c2[mi][ni][3] + b2b, 0.f);
        yp[mi*2  ][0] += z0*w00 + z1*w01;
        yp[mi*2  ][1] += z0*w10 + z1*w11;
        yp[mi*2+1][0] += z2*w00 + z3*w01;
        yp[mi*2+1][1] += z2*w10 + z3*w11;
      }
    }
  }
  #pragma unroll
  for (int m = 1; m <= 2; m <<= 1){
    #pragma unroll
    for (int r = 0; r < 4; r++){
      yp[r][0] += __shfl_xor_sync(0xffffffffu, yp[r][0], m);
      yp[r][1] += __shfl_xor_sync(0xffffffffu, yp[r][1], m);
    }
  }
  if ((lane & 3) == 0){
    float b30 = __ldg(b3), b31 = __ldg(b3 + 1);
    #pragma unroll
    for (int r = 0; r < 4; r++){
      int row = (r >> 1)*16 + (r & 1)*8 + (lane >> 2);
      float y0 = yp[r][0] + b30;
      float y1 = yp[r][1] + b31;
      float mm  = fmaxf(y0, y1);
      float lse = mm + __logf(__expf(y0 - mm) + __expf(y1 - mm));
      ((float2*)out)[blockIdx.x*128 + wid*32 + row] = make_float2(y0 - lse, y1 - lse);
    }
  }
}

extern "C" void kernel_launch(void* const* d_in, const int* in_sizes, int n_in,
                              void* d_out, int out_size)
{
  const float* X   = (const float*)d_in[0];
  const float* Wih = (const float*)d_in[1];
  const float* Whh = (const float*)d_in[2];
  const float* bih = (const float*)d_in[3];
  const float* bhh = (const float*)d_in[4];
  const float* W1  = (const float*)d_in[5];
  const float* b1  = (const float*)d_in[6];
  const float* W2  = (const float*)d_in[7];
  const float* b2  = (const float*)d_in[8];
  const float* W3  = (const float*)d_in[9];
  const float* b3  = (const float*)d_in[10];

  gates_kernel<<<512, 512>>>(X, Wih, bih, bhh);

  cudaFuncSetAttribute(scan_kernel, cudaFuncAttributeMaxDynamicSharedMemorySize, SMEM_TOT);
  scan_kernel<<<NB / 128, 128, SMEM_TOT>>>(Whh, W1, b1, W2, b2, W3, b3, (float*)d_out);
}